// round 2
// baseline (speedup 1.0000x reference)
#include <cuda_runtime.h>

#define HW 16384

// ---------------- scratch (static device allocations, allowed) ----------------
__device__ float g_a[2*4*HW];        // conv1x1 chain output (2,4,128,128)
__device__ float g_att[2*4*HW];      // grid attention output
__device__ float g_y[2*64*HW];       // y = x + proj(att)
__device__ float g_h1[2*16*HW];      // ff first relu
__device__ float g_h2[2*16*HW];      // ff conv relu
__device__ float g_q[32*1536*4];     // normalized qk per token
__device__ float g_Gp[32*4*175];     // partial Gram matrices (35 feats x 5 cols, 4 segs)
__device__ float g_sums[4];          // per-batch sum, sumsq of a
__device__ float g_stats[4];         // per-batch mu, rsigma
__device__ float g_weff1[4*64];
__device__ float g_beff1[4];
__device__ float g_weff2[64*4];
__device__ float g_beff2[64];

// ---------------- weight fusion + zero sums ----------------
__global__ void prep_kernel(const float* __restrict__ w1a, const float* __restrict__ b1a,
                            const float* __restrict__ w1b, const float* __restrict__ b1b,
                            const float* __restrict__ w2,  const float* __restrict__ b2,
                            const float* __restrict__ wc,  const float* __restrict__ bc) {
    int t = threadIdx.x;
    if (t < 4) g_sums[t] = 0.f;
    if (t < 256) {
        int ck = t >> 6, c = t & 63;
        float s = 0.f;
        #pragma unroll
        for (int j = 0; j < 4; j++) s += w1b[ck*4+j] * w1a[j*64+c];
        g_weff1[ck*64+c] = s;
    }
    if (t < 4) {
        float s = b1b[t];
        #pragma unroll
        for (int j = 0; j < 4; j++) s += w1b[t*4+j] * b1a[j];
        g_beff1[t] = s;
    }
    if (t < 256) {
        int o = t >> 2, ck = t & 3;
        float s = 0.f;
        for (int c = 0; c < 64; c++) s += wc[o*64+c] * w2[c*4+ck];
        g_weff2[o*4+ck] = s;
    }
    if (t < 64) {
        float s = bc[t];
        for (int c = 0; c < 64; c++) s += wc[t*64+c] * b2[c];
        g_beff2[t] = s;
    }
}

// ---------------- a = fused conv1x1 chain, plus per-batch sum/sumsq ----------------
__global__ void a_kernel(const float* __restrict__ x) {
    __shared__ float sw[256];
    __shared__ float sb[4];
    __shared__ float red[256];
    int t = threadIdx.x;
    sw[t] = g_weff1[t];
    if (t < 4) sb[t] = g_beff1[t];
    __syncthreads();
    int gid = blockIdx.x * 256 + t;
    int b = gid >> 14, pix = gid & 16383;
    const float* xp = x + b*64*HW + pix;
    float a0 = sb[0], a1 = sb[1], a2 = sb[2], a3 = sb[3];
    #pragma unroll
    for (int c = 0; c < 64; c++) {
        float xv = xp[c*HW];
        a0 += sw[c]*xv; a1 += sw[64+c]*xv; a2 += sw[128+c]*xv; a3 += sw[192+c]*xv;
    }
    float* ap = g_a + b*4*HW + pix;
    ap[0] = a0; ap[HW] = a1; ap[2*HW] = a2; ap[3*HW] = a3;

    float s  = a0+a1+a2+a3;
    float sq = a0*a0+a1*a1+a2*a2+a3*a3;
    red[t] = s; __syncthreads();
    for (int o = 128; o > 0; o >>= 1) { if (t < o) red[t] += red[t+o]; __syncthreads(); }
    if (t == 0) atomicAdd(&g_sums[b*2], red[0]);
    __syncthreads();
    red[t] = sq; __syncthreads();
    for (int o = 128; o > 0; o >>= 1) { if (t < o) red[t] += red[t+o]; __syncthreads(); }
    if (t == 0) atomicAdd(&g_sums[b*2+1], red[0]);
}

__global__ void stats_kernel() {
    int b = threadIdx.x;
    if (b < 2) {
        const float n = 4.f * 192.f * 128.f;   // padded element count
        float mu  = g_sums[b*2] / n;
        float var = g_sums[b*2+1] / n - mu*mu;
        g_stats[b*2]   = mu;
        g_stats[b*2+1] = rsqrtf(var + 1e-5f);
    }
}

// ---------------- attention pass 1: gather tokens, compute q, partial Gram ----------------
// Attention batch batch2 = b*16 + (c_idx*4 + f1). Token l = gh*32+gw, channel k = f2.
// token value = ((r>=64 ? a[b,c_idx,r-64,gw*4+k] : 0) - mu) * rsig, r = gh*4+f1.
// E_lm ~ exp(alpha * q_l.q_m) approximated by degree-3 Taylor -> 35 monomial features.
__global__ void attn1_kernel(const float* __restrict__ wqk) {
    __shared__ float sq[384*4], st[384*4];
    __shared__ float swqk[16];
    int t = threadIdx.x;               // 0..383
    int seg = blockIdx.x;              // 0..3 (token segment of 384)
    int batch2 = blockIdx.y;           // 0..31
    int b = batch2 >> 4, j = batch2 & 15;
    int c_idx = j >> 2, f1 = j & 3;
    if (t < 16) swqk[t] = wqk[t];
    __syncthreads();
    float mu = g_stats[b*2], rs = g_stats[b*2+1];

    int l = seg*384 + t;
    {
        int gh = l >> 5, gw = l & 31;
        int r = gh*4 + f1;
        float t0, t1, t2, t3;
        if (r >= 64) {
            float4 v = *reinterpret_cast<const float4*>(
                &g_a[((b*4 + c_idx)*128 + (r-64))*128 + gw*4]);
            t0 = (v.x - mu)*rs; t1 = (v.y - mu)*rs; t2 = (v.z - mu)*rs; t3 = (v.w - mu)*rs;
        } else {
            float p = -mu*rs; t0 = t1 = t2 = t3 = p;
        }
        float q0 = t0*swqk[0] + t1*swqk[4] + t2*swqk[8]  + t3*swqk[12];
        float q1 = t0*swqk[1] + t1*swqk[5] + t2*swqk[9]  + t3*swqk[13];
        float q2 = t0*swqk[2] + t1*swqk[6] + t2*swqk[10] + t3*swqk[14];
        float q3 = t0*swqk[3] + t1*swqk[7] + t2*swqk[11] + t3*swqk[15];
        float inv = 1.f / (sqrtf(q0*q0 + q1*q1 + q2*q2 + q3*q3) + 1e-8f);
        q0 *= inv; q1 *= inv; q2 *= inv; q3 *= inv;
        st[t*4+0] = t0; st[t*4+1] = t1; st[t*4+2] = t2; st[t*4+3] = t3;
        sq[t*4+0] = q0; sq[t*4+1] = q1; sq[t*4+2] = q2; sq[t*4+3] = q3;
        *reinterpret_cast<float4*>(&g_q[(batch2*1536 + l)*4]) = make_float4(q0,q1,q2,q3);
    }
    __syncthreads();

    if (t < 175) {                     // entry = feature(35) x M-column(5)
        int fi = t / 5, mi = t - fi*5;
        int E0=0, E1=0, E2=0, E3=0;
        {
            int f = 0;
            for (int a = 0; a <= 3; a++)
             for (int bb = 0; bb + a <= 3; bb++)
              for (int c = 0; c + a + bb <= 3; c++)
               for (int d = 0; d + a + bb + c <= 3; d++) {
                  if (f == fi) { E0=a; E1=bb; E2=c; E3=d; }
                  f++;
               }
        }
        const float invfact[4] = {1.f, 1.f, 0.5f, 0.16666666667f};
        const float ALPHA = 0.17677669529663687f;   // 1/sqrt(32)
        int deg = E0+E1+E2+E3;
        float coef = invfact[E0]*invfact[E1]*invfact[E2]*invfact[E3];
        for (int k = 0; k < deg; k++) coef *= ALPHA;

        float sum = 0.f;
        for (int lt = 0; lt < 384; lt++) {
            float q0 = sq[lt*4], q1 = sq[lt*4+1], q2 = sq[lt*4+2], q3 = sq[lt*4+3];
            float m = coef;
            if (E0 > 0) m *= q0; if (E0 > 1) m *= q0; if (E0 > 2) m *= q0;
            if (E1 > 0) m *= q1; if (E1 > 1) m *= q1; if (E1 > 2) m *= q1;
            if (E2 > 0) m *= q2; if (E2 > 1) m *= q2; if (E2 > 2) m *= q2;
            if (E3 > 0) m *= q3; if (E3 > 1) m *= q3; if (E3 > 2) m *= q3;
            float mv = (mi < 4) ? st[lt*4 + mi] : 1.f;
            sum += m * mv;
        }
        g_Gp[(batch2*4 + seg)*175 + t] = sum;
    }
}

// ---------------- attention pass 2: out_l = phi(q_l) . G, normalize, scatter ----------------
__global__ void attn2_kernel() {
    __shared__ float sG[175];
    int t = threadIdx.x;               // 0..1023, only tokens l<1024 produce output
    int batch2 = blockIdx.x;
    if (t < 175) {
        float s = 0.f;
        #pragma unroll
        for (int sgi = 0; sgi < 4; sgi++) s += g_Gp[(batch2*4 + sgi)*175 + t];
        sG[t] = s;
    }
    __syncthreads();

    int l = t;
    float4 qv = *reinterpret_cast<const float4*>(&g_q[(batch2*1536 + l)*4]);
    float q0 = qv.x, q1 = qv.y, q2 = qv.z, q3 = qv.w;
    float a0=0.f, a1=0.f, a2=0.f, a3=0.f, a4=0.f;
    int f = 0;
    float p0 = 1.f;
    #pragma unroll
    for (int e0 = 0; e0 <= 3; e0++) {
        float p1 = p0;
        #pragma unroll
        for (int e1 = 0; e1 <= 3-e0; e1++) {
            float p2 = p1;
            #pragma unroll
            for (int e2 = 0; e2 <= 3-e0-e1; e2++) {
                float p3 = p2;
                #pragma unroll
                for (int e3 = 0; e3 <= 3-e0-e1-e2; e3++) {
                    a0 += p3 * sG[f*5+0];
                    a1 += p3 * sG[f*5+1];
                    a2 += p3 * sG[f*5+2];
                    a3 += p3 * sG[f*5+3];
                    a4 += p3 * sG[f*5+4];
                    f++;
                    p3 *= q3;
                }
                p2 *= q2;
            }
            p1 *= q1;
        }
        p0 *= q0;
    }
    float inv = 1.f / a4;
    int b = batch2 >> 4, j = batch2 & 15;
    int c_idx = j >> 2, f1 = j & 3;
    int gh = l >> 5, gw = l & 31;
    int row = gh*4 + c_idx, col = gw*4 + f1;
    float* ap = g_att + (b*4*128 + row)*128 + col;
    ap[0]       = a0*inv;
    ap[HW]      = a1*inv;
    ap[2*HW]    = a2*inv;
    ap[3*HW]    = a3*inv;
}

// ---------------- y = x + proj(att); h1 = relu(wf1 @ y + bf1) ----------------
__global__ void y_h1_kernel(const float* __restrict__ x,
                            const float* __restrict__ wf1, const float* __restrict__ bf1) {
    __shared__ float swe[256], sbe[64], swf1[1024], sbf1[16];
    int t = threadIdx.x;
    swe[t] = g_weff2[t];
    if (t < 64) sbe[t] = g_beff2[t];
    for (int i = t; i < 1024; i += 256) swf1[i] = wf1[i];
    if (t < 16) sbf1[t] = bf1[t];
    __syncthreads();
    int gid = blockIdx.x*256 + t;
    int b = gid >> 14, pix = gid & 16383;
    const float* atp = g_att + b*4*HW + pix;
    float at0 = atp[0], at1 = atp[HW], at2 = atp[2*HW], at3 = atp[3*HW];
    float acc[16];
    #pragma unroll
    for (int m = 0; m < 16; m++) acc[m] = 0.f;
    const float* xp = x   + b*64*HW + pix;
    float*       yp = g_y + b*64*HW + pix;
    #pragma unroll 4
    for (int o = 0; o < 64; o++) {
        float yv = xp[o*HW] + sbe[o]
                 + swe[o*4]*at0 + swe[o*4+1]*at1 + swe[o*4+2]*at2 + swe[o*4+3]*at3;
        yp[o*HW] = yv;
        #pragma unroll
        for (int m = 0; m < 16; m++) acc[m] += swf1[m*64+o] * yv;
    }
    float* hp = g_h1 + b*16*HW + pix;
    #pragma unroll
    for (int m = 0; m < 16; m++) hp[m*HW] = fmaxf(acc[m] + sbf1[m], 0.f);
}

// ---------------- dilated 3x3 conv (stride-2 dilation, custom top pad) + relu ----------------
__global__ void h2_kernel(const float* __restrict__ wf2, const float* __restrict__ bf2) {
    __shared__ float sw[2304], sb[16];
    int t = threadIdx.x;
    for (int i = t; i < 2304; i += 256) sw[i] = wf2[i];
    if (t < 16) sb[t] = bf2[t];
    __syncthreads();
    int gid = blockIdx.x*256 + t;
    int b = gid >> 14, pix = gid & 16383;
    int h = pix >> 7, w = pix & 127;
    float acc[16];
    #pragma unroll
    for (int m = 0; m < 16; m++) acc[m] = 0.f;
    const float* h1b = g_h1 + b*16*HW;
    #pragma unroll
    for (int kh = 0; kh < 3; kh++) {
        int row = h - 5 + 2*kh;                 // (top pad 3) + (conv pad 2) + dilation 2
        if (row < 0 || row >= 128) continue;
        #pragma unroll
        for (int kw = 0; kw < 3; kw++) {
            int col = w - 2 + 2*kw;
            if (col < 0 || col >= 128) continue;
            #pragma unroll
            for (int ci = 0; ci < 16; ci++) {
                float v = h1b[ci*HW + row*128 + col];
                #pragma unroll
                for (int m = 0; m < 16; m++)
                    acc[m] += sw[((m*16+ci)*3 + kh)*3 + kw] * v;
            }
        }
    }
    float* hp = g_h2 + b*16*HW + pix;
    #pragma unroll
    for (int m = 0; m < 16; m++) hp[m*HW] = fmaxf(acc[m] + sb[m], 0.f);
}

// ---------------- out = y + wf3 @ h2 + bf3 ----------------
__global__ void out_kernel(const float* __restrict__ wf3, const float* __restrict__ bf3,
                           float* __restrict__ out) {
    __shared__ float sw[1024], sb[64];
    int t = threadIdx.x;
    for (int i = t; i < 1024; i += 256) sw[i] = wf3[i];
    if (t < 64) sb[t] = bf3[t];
    __syncthreads();
    int gid = blockIdx.x*256 + t;
    int b = gid >> 14, pix = gid & 16383;
    const float* hp = g_h2 + b*16*HW + pix;
    float h2v[16];
    #pragma unroll
    for (int m = 0; m < 16; m++) h2v[m] = hp[m*HW];
    const float* yp = g_y + b*64*HW + pix;
    float*       op = out + b*64*HW + pix;
    #pragma unroll 4
    for (int o = 0; o < 64; o++) {
        float s = yp[o*HW] + sb[o];
        #pragma unroll
        for (int m = 0; m < 16; m++) s += sw[o*16+m] * h2v[m];
        op[o*HW] = s;
    }
}

extern "C" void kernel_launch(void* const* d_in, const int* in_sizes, int n_in,
                              void* d_out, int out_size) {
    const float* x   = (const float*)d_in[0];
    const float* w1a = (const float*)d_in[1];
    const float* b1a = (const float*)d_in[2];
    const float* w1b = (const float*)d_in[3];
    const float* b1b = (const float*)d_in[4];
    const float* wqk = (const float*)d_in[5];
    const float* w2  = (const float*)d_in[6];
    const float* b2  = (const float*)d_in[7];
    const float* wc  = (const float*)d_in[8];
    const float* bc  = (const float*)d_in[9];
    const float* wf1 = (const float*)d_in[10];
    const float* bf1 = (const float*)d_in[11];
    const float* wf2 = (const float*)d_in[12];
    const float* bf2 = (const float*)d_in[13];
    const float* wf3 = (const float*)d_in[14];
    const float* bf3 = (const float*)d_in[15];
    float* out = (float*)d_out;

    prep_kernel <<<1, 256>>>(w1a, b1a, w1b, b1b, w2, b2, wc, bc);
    a_kernel    <<<128, 256>>>(x);
    stats_kernel<<<1, 32>>>();
    attn1_kernel<<<dim3(4, 32), 384>>>(wqk);
    attn2_kernel<<<32, 1024>>>();
    y_h1_kernel <<<128, 256>>>(x, wf1, bf1);
    h2_kernel   <<<128, 256>>>(wf2, bf2);
    out_kernel  <<<128, 256>>>(wf3, bf3, out);
}

// round 3
// speedup vs baseline: 1.3933x; 1.3933x over previous
#include <cuda_runtime.h>

#define HW 16384
#define ALPHA 0.17677669529663687f   /* 1/sqrt(32); ALPHA^2 = 1/32 */

// ---------------- scratch ----------------
__device__ float g_a[2*4*HW];        // conv1x1 chain output (2,4,128,128)
__device__ float g_att[2*4*HW];      // grid attention output
__device__ float g_y[2*64*HW];       // y = x + proj(att)
__device__ float g_h1[2*16*HW];      // ff first relu
__device__ float g_q[32*1536*4];     // normalized qk per token
__device__ float g_Gp[32*4*75];      // partial Gram matrices (15 feats x 5 cols, 4 segs)
__device__ float g_part[128*2];      // per-block (sum, sumsq) of a

// ---------------- a = fused conv1x1 chain + per-block sum/sumsq ----------------
__global__ void a_kernel(const float* __restrict__ x,
                         const float* __restrict__ w1a, const float* __restrict__ b1a,
                         const float* __restrict__ w1b, const float* __restrict__ b1b) {
    __shared__ float sw[256];
    __shared__ float sb[4];
    __shared__ float rs[8], rq[8];
    int t = threadIdx.x;
    // inline weight fusion: weff[ck][c] = sum_j w1b[ck][j] * w1a[j][c]
    {
        int ck = t >> 6, c = t & 63;
        float s = 0.f;
        #pragma unroll
        for (int j = 0; j < 4; j++) s += w1b[ck*4+j] * w1a[j*64+c];
        sw[ck*64+c] = s;
    }
    if (t < 4) {
        float s = b1b[t];
        #pragma unroll
        for (int j = 0; j < 4; j++) s += w1b[t*4+j] * b1a[j];
        sb[t] = s;
    }
    __syncthreads();
    int gid = blockIdx.x * 256 + t;
    int b = gid >> 14, pix = gid & 16383;
    const float* xp = x + b*64*HW + pix;
    float a0 = sb[0], a1 = sb[1], a2 = sb[2], a3 = sb[3];
    #pragma unroll
    for (int c = 0; c < 64; c++) {
        float xv = xp[c*HW];
        a0 += sw[c]*xv; a1 += sw[64+c]*xv; a2 += sw[128+c]*xv; a3 += sw[192+c]*xv;
    }
    float* ap = g_a + b*4*HW + pix;
    ap[0] = a0; ap[HW] = a1; ap[2*HW] = a2; ap[3*HW] = a3;

    float s  = a0+a1+a2+a3;
    float sq = a0*a0+a1*a1+a2*a2+a3*a3;
    #pragma unroll
    for (int o = 16; o > 0; o >>= 1) {
        s  += __shfl_down_sync(0xffffffffu, s,  o);
        sq += __shfl_down_sync(0xffffffffu, sq, o);
    }
    int wid = t >> 5, lane = t & 31;
    if (lane == 0) { rs[wid] = s; rq[wid] = sq; }
    __syncthreads();
    if (t == 0) {
        float ts = 0.f, tq = 0.f;
        #pragma unroll
        for (int w = 0; w < 8; w++) { ts += rs[w]; tq += rq[w]; }
        g_part[blockIdx.x*2]   = ts;
        g_part[blockIdx.x*2+1] = tq;
    }
}

// ---------------- attention pass 1 ----------------
// attention batch batch2 = b*16 + (c_idx*4 + f1). Token l = gh*32+gw (gh<48).
// token value k = ((r>=64 ? a[b,c_idx,r-64,gw*4+k] : 0) - mu) * rsig, r = gh*4+f1.
// exp(alpha*u), u=q_l.q_m, approximated degree-2 -> 15 monomial features (coef folded).
__global__ void attn1_kernel(const float* __restrict__ wqk) {
    __shared__ float st[384*4];
    __shared__ float sphi[384*16];     // 15 used, pad to 16
    __shared__ float swqk[16];
    __shared__ float sstat[2];         // mu, rsigma
    __shared__ float sGc[4*80];        // per-chunk Gram partials (75 used, pad 80)
    int t = threadIdx.x;               // 0..383
    int seg = blockIdx.x;              // 0..3 (token segment of 384)
    int batch2 = blockIdx.y;           // 0..31
    int b = batch2 >> 4, j = batch2 & 15;
    int c_idx = j >> 2, f1 = j & 3;
    if (t >= 352 && t < 368) swqk[t-352] = wqk[t-352];

    // stats from per-block partials (warp 0)
    if (t < 32) {
        float s  = g_part[(b*64 + t)*2]     + g_part[(b*64 + t + 32)*2];
        float sq = g_part[(b*64 + t)*2 + 1] + g_part[(b*64 + t + 32)*2 + 1];
        #pragma unroll
        for (int o = 16; o > 0; o >>= 1) {
            s  += __shfl_down_sync(0xffffffffu, s,  o);
            sq += __shfl_down_sync(0xffffffffu, sq, o);
        }
        if (t == 0) {
            const float n = 4.f * 192.f * 128.f;
            float mu  = s / n;
            float var = sq / n - mu*mu;
            sstat[0] = mu;
            sstat[1] = rsqrtf(var + 1e-5f);
        }
    }

    // raw token load (before stats are needed)
    int l = seg*384 + t;
    int gh = l >> 5, gw = l & 31;
    int r = gh*4 + f1;
    float v0 = 0.f, v1 = 0.f, v2 = 0.f, v3 = 0.f;
    if (r >= 64) {
        float4 v = *reinterpret_cast<const float4*>(
            &g_a[((b*4 + c_idx)*128 + (r-64))*128 + gw*4]);
        v0 = v.x; v1 = v.y; v2 = v.z; v3 = v.w;
    }
    __syncthreads();
    {
        float mu = sstat[0], rsg = sstat[1];
        float t0 = (v0 - mu)*rsg, t1 = (v1 - mu)*rsg, t2 = (v2 - mu)*rsg, t3 = (v3 - mu)*rsg;
        float q0 = t0*swqk[0] + t1*swqk[4] + t2*swqk[8]  + t3*swqk[12];
        float q1 = t0*swqk[1] + t1*swqk[5] + t2*swqk[9]  + t3*swqk[13];
        float q2 = t0*swqk[2] + t1*swqk[6] + t2*swqk[10] + t3*swqk[14];
        float q3 = t0*swqk[3] + t1*swqk[7] + t2*swqk[11] + t3*swqk[15];
        float inv = 1.f / (sqrtf(q0*q0 + q1*q1 + q2*q2 + q3*q3) + 1e-8f);
        q0 *= inv; q1 *= inv; q2 *= inv; q3 *= inv;
        st[t*4+0] = t0; st[t*4+1] = t1; st[t*4+2] = t2; st[t*4+3] = t3;
        float* ph = &sphi[t*16];
        ph[0]  = 1.f;
        ph[1]  = ALPHA * q3;
        ph[2]  = 0.015625f * q3*q3;
        ph[3]  = ALPHA * q2;
        ph[4]  = 0.03125f  * q2*q3;
        ph[5]  = 0.015625f * q2*q2;
        ph[6]  = ALPHA * q1;
        ph[7]  = 0.03125f  * q1*q3;
        ph[8]  = 0.03125f  * q1*q2;
        ph[9]  = 0.015625f * q1*q1;
        ph[10] = ALPHA * q0;
        ph[11] = 0.03125f  * q0*q3;
        ph[12] = 0.03125f  * q0*q2;
        ph[13] = 0.03125f  * q0*q1;
        ph[14] = 0.015625f * q0*q0;
        *reinterpret_cast<float4*>(&g_q[(batch2*1536 + l)*4]) = make_float4(q0,q1,q2,q3);
    }
    __syncthreads();

    // phase 2: 300 threads = 4 chunks x 75 outputs, 96 tokens each
    if (t < 300) {
        int chunk = t / 75, out = t - chunk*75;
        int fi = out / 5, mi = out - fi*5;
        int base = chunk * 96;
        float sum = 0.f;
        #pragma unroll 4
        for (int i = 0; i < 96; i++) {
            int lt = base + i;
            float m  = sphi[lt*16 + fi];
            float mv = (mi < 4) ? st[lt*4 + mi] : 1.f;
            sum += m * mv;
        }
        sGc[chunk*80 + out] = sum;
    }
    __syncthreads();
    if (t < 75) {
        float g = sGc[t] + sGc[80+t] + sGc[160+t] + sGc[240+t];
        g_Gp[(batch2*4 + seg)*75 + t] = g;
    }
}

// ---------------- attention pass 2: out_l = phi(q_l) . G, normalize, scatter ----------------
__global__ void attn2_kernel() {
    __shared__ float sG[75];
    int t = threadIdx.x;               // 0..1023, tokens l<1024 produce output
    int batch2 = blockIdx.x;
    if (t < 75) {
        float s = 0.f;
        #pragma unroll
        for (int sgi = 0; sgi < 4; sgi++) s += g_Gp[(batch2*4 + sgi)*75 + t];
        sG[t] = s;
    }
    __syncthreads();

    int l = t;
    float4 qv = *reinterpret_cast<const float4*>(&g_q[(batch2*1536 + l)*4]);
    float q0 = qv.x, q1 = qv.y, q2 = qv.z, q3 = qv.w;
    float a0=0.f, a1=0.f, a2=0.f, a3=0.f, a4=0.f;
    // monomials in same enumeration order (raw, coef already folded into G)
    float mono[15];
    mono[0]  = 1.f;
    mono[1]  = q3;
    mono[2]  = q3*q3;
    mono[3]  = q2;
    mono[4]  = q2*q3;
    mono[5]  = q2*q2;
    mono[6]  = q1;
    mono[7]  = q1*q3;
    mono[8]  = q1*q2;
    mono[9]  = q1*q1;
    mono[10] = q0;
    mono[11] = q0*q3;
    mono[12] = q0*q2;
    mono[13] = q0*q1;
    mono[14] = q0*q0;
    #pragma unroll
    for (int f = 0; f < 15; f++) {
        float m = mono[f];
        a0 += m * sG[f*5+0];
        a1 += m * sG[f*5+1];
        a2 += m * sG[f*5+2];
        a3 += m * sG[f*5+3];
        a4 += m * sG[f*5+4];
    }
    float inv = 1.f / a4;
    int b = batch2 >> 4, j = batch2 & 15;
    int c_idx = j >> 2, f1 = j & 3;
    int gh = l >> 5, gw = l & 31;
    int row = gh*4 + c_idx, col = gw*4 + f1;
    float* ap = g_att + (b*4*128 + row)*128 + col;
    ap[0]    = a0*inv;
    ap[HW]   = a1*inv;
    ap[2*HW] = a2*inv;
    ap[3*HW] = a3*inv;
}

// ---------------- y = x + proj(att); h1 = relu(wf1 @ y + bf1) ----------------
__global__ void y_h1_kernel(const float* __restrict__ x,
                            const float* __restrict__ w2,  const float* __restrict__ b2,
                            const float* __restrict__ wc,  const float* __restrict__ bc,
                            const float* __restrict__ wf1, const float* __restrict__ bf1) {
    __shared__ float swe[256], sbe[64], swf1[1024], sbf1[16];
    int t = threadIdx.x;
    // inline fused projection weights: weff[o][ck] = sum_c wc[o][c]*w2[c][ck]
    {
        int o = t >> 2, ck = t & 3;
        float s = 0.f;
        for (int c = 0; c < 64; c++) s += wc[o*64+c] * w2[c*4+ck];
        swe[o*4+ck] = s;
    }
    if (t < 64) {
        float s = bc[t];
        for (int c = 0; c < 64; c++) s += wc[t*64+c] * b2[c];
        sbe[t] = s;
    }
    for (int i = t; i < 1024; i += 256) swf1[i] = wf1[i];
    if (t < 16) sbf1[t] = bf1[t];
    __syncthreads();
    int gid = blockIdx.x*256 + t;
    int b = gid >> 14, pix = gid & 16383;
    const float* atp = g_att + b*4*HW + pix;
    float at0 = atp[0], at1 = atp[HW], at2 = atp[2*HW], at3 = atp[3*HW];
    float acc[16];
    #pragma unroll
    for (int m = 0; m < 16; m++) acc[m] = 0.f;
    const float* xp = x   + b*64*HW + pix;
    float*       yp = g_y + b*64*HW + pix;
    #pragma unroll 4
    for (int o = 0; o < 64; o++) {
        float yv = xp[o*HW] + sbe[o]
                 + swe[o*4]*at0 + swe[o*4+1]*at1 + swe[o*4+2]*at2 + swe[o*4+3]*at3;
        yp[o*HW] = yv;
        #pragma unroll
        for (int m = 0; m < 16; m++) acc[m] += swf1[m*64+o] * yv;
    }
    float* hp = g_h1 + b*16*HW + pix;
    #pragma unroll
    for (int m = 0; m < 16; m++) hp[m*HW] = fmaxf(acc[m] + sbf1[m], 0.f);
}

// ---------------- fused: dilated 3x3 conv + relu + final 1x1 + residual ----------------
__global__ void h2out_kernel(const float* __restrict__ wf2, const float* __restrict__ bf2,
                             const float* __restrict__ wf3, const float* __restrict__ bf3,
                             float* __restrict__ out) {
    __shared__ float sw[2304], sb[16], sw3[1024], sb3[64];
    int t = threadIdx.x;
    for (int i = t; i < 2304; i += 256) sw[i] = wf2[i];
    for (int i = t; i < 1024; i += 256) sw3[i] = wf3[i];
    if (t < 16) sb[t] = bf2[t];
    if (t < 64) sb3[t] = bf3[t];
    __syncthreads();
    int gid = blockIdx.x*256 + t;
    int b = gid >> 14, pix = gid & 16383;
    int h = pix >> 7, w = pix & 127;
    float acc[16];
    #pragma unroll
    for (int m = 0; m < 16; m++) acc[m] = 0.f;
    const float* h1b = g_h1 + b*16*HW;
    #pragma unroll
    for (int kh = 0; kh < 3; kh++) {
        int row = h - 5 + 2*kh;                 // (top pad 3) + (conv pad 2), dilation 2
        if (row < 0 || row >= 128) continue;
        #pragma unroll
        for (int kw = 0; kw < 3; kw++) {
            int col = w - 2 + 2*kw;
            if (col < 0 || col >= 128) continue;
            #pragma unroll
            for (int ci = 0; ci < 16; ci++) {
                float v = h1b[ci*HW + row*128 + col];
                #pragma unroll
                for (int m = 0; m < 16; m++)
                    acc[m] += sw[((m*16+ci)*3 + kh)*3 + kw] * v;
            }
        }
    }
    #pragma unroll
    for (int m = 0; m < 16; m++) acc[m] = fmaxf(acc[m] + sb[m], 0.f);

    const float* yp = g_y + b*64*HW + pix;
    float*       op = out + b*64*HW + pix;
    #pragma unroll 4
    for (int o = 0; o < 64; o++) {
        float s = yp[o*HW] + sb3[o];
        #pragma unroll
        for (int m = 0; m < 16; m++) s += sw3[o*16+m] * acc[m];
        op[o*HW] = s;
    }
}

extern "C" void kernel_launch(void* const* d_in, const int* in_sizes, int n_in,
                              void* d_out, int out_size) {
    const float* x   = (const float*)d_in[0];
    const float* w1a = (const float*)d_in[1];
    const float* b1a = (const float*)d_in[2];
    const float* w1b = (const float*)d_in[3];
    const float* b1b = (const float*)d_in[4];
    const float* wqk = (const float*)d_in[5];
    const float* w2  = (const float*)d_in[6];
    const float* b2  = (const float*)d_in[7];
    const float* wc  = (const float*)d_in[8];
    const float* bc  = (const float*)d_in[9];
    const float* wf1 = (const float*)d_in[10];
    const float* bf1 = (const float*)d_in[11];
    const float* wf2 = (const float*)d_in[12];
    const float* bf2 = (const float*)d_in[13];
    const float* wf3 = (const float*)d_in[14];
    const float* bf3 = (const float*)d_in[15];
    float* out = (float*)d_out;

    a_kernel    <<<128, 256>>>(x, w1a, b1a, w1b, b1b);
    attn1_kernel<<<dim3(4, 32), 384>>>(wqk);
    attn2_kernel<<<32, 1024>>>();
    y_h1_kernel <<<128, 256>>>(x, w2, b2, wc, bc, wf1, bf1);
    h2out_kernel<<<128, 256>>>(wf2, bf2, wf3, bf3, out);
}